// round 7
// baseline (speedup 1.0000x reference)
#include <cuda_runtime.h>
#include <cstdint>

// ---------------- problem constants ----------------
#define BATCH   16
#define SEQ     2048
#define INP     256
#define HID     1024
#define MAXNZ   64
#define NCTA    64
#define NTHR    256
#define OUT_MAIN (BATCH*SEQ*INP)        // 8388608
#define HT_ELEMS (2*BATCH*HID)          // 32768
#define SQRT10  3.1622776601683795f

// ---------------- device scratch (no allocs allowed) ----------------
__device__ float          g_xT[(size_t)SEQ*INP*BATCH];       // [t][j][b]
__device__ float          g_outsT[(size_t)SEQ*HID*BATCH];    // [t][i][b]  (h1 per step)
__device__ float          g_h0[2][HID*BATCH];                // layer0 state ping-pong
__device__ float          g_WT[HID*INP];                     // out_w transposed [i][o]
__device__ unsigned short g_idx[3][HID][MAXNZ];              // 0: ih0, 1: hh0, 2: hh1
__device__ float          g_val[3][HID][MAXNZ];
__device__ int            g_cnt[3][HID];
__device__ unsigned int   g_slots[NCTA];                     // per-CTA phase counters

// ---------------- small helpers ----------------
__device__ __forceinline__ unsigned long long pk2(float lo, float hi) {
    unsigned long long r;
    asm("mov.b64 %0, {%1,%2};" : "=l"(r) : "f"(lo), "f"(hi));
    return r;
}
__device__ __forceinline__ void upk2(unsigned long long v, float& lo, float& hi) {
    asm("mov.b64 {%0,%1}, %2;" : "=f"(lo), "=f"(hi) : "l"(v));
}
__device__ __forceinline__ void fma2(unsigned long long& d, unsigned long long a, unsigned long long b) {
    asm("fma.rn.f32x2 %0, %1, %2, %3;" : "=l"(d) : "l"(a), "l"(b), "l"(d));
}
__device__ __forceinline__ unsigned ld_relax(const unsigned* p) {
    unsigned v;
    asm volatile("ld.relaxed.gpu.global.u32 %0, [%1];" : "=r"(v) : "l"(p) : "memory");
    return v;
}
__device__ __forceinline__ unsigned ld_acq(const unsigned* p) {
    unsigned v;
    asm volatile("ld.acquire.gpu.global.u32 %0, [%1];" : "=r"(v) : "l"(p) : "memory");
    return v;
}
__device__ __forceinline__ void st_rel(unsigned* p, unsigned v) {
    asm volatile("st.release.gpu.global.u32 [%0], %1;" :: "l"(p), "r"(v) : "memory");
}

// wait until all 64 slots >= tgt. Relaxed polling; acquire confirm once.
__device__ __forceinline__ void wait_all(unsigned tgt) {
    if (threadIdx.x < 32) {
        int l = threadIdx.x;
        const unsigned* s = (const unsigned*)g_slots;
        for (;;) {
            unsigned a = ld_relax(s + l);
            unsigned c = ld_relax(s + l + 32);
            if (__all_sync(0xffffffffu, (a >= tgt) && (c >= tgt))) break;
        }
        ld_acq(s + l);          // synchronize-with producers (monotonic counters)
        ld_acq(s + l + 32);
    }
    __syncthreads();
}

// ---------------- kernel: zero counters ----------------
__global__ void k_zero_slots() {
    if (threadIdx.x < NCTA) g_slots[threadIdx.x] = 0u;
}

// ---------------- kernel: transpose x [b][t][j] -> xT [t][j][b] ----------------
__global__ void k_xT(const float* __restrict__ x) {
    __shared__ float sm[INP * 17];
    int t = blockIdx.x;
    int tid = threadIdx.x;
    #pragma unroll
    for (int bb = 0; bb < BATCH; bb++) {
        sm[tid * 17 + bb] = x[(size_t)bb * SEQ * INP + (size_t)t * INP + tid];
    }
    __syncthreads();
    float* dst = g_xT + (size_t)t * (INP * BATCH);
    #pragma unroll
    for (int k = 0; k < 16; k++) {
        int f = k * 256 + tid;            // f = j*16 + b
        dst[f] = sm[(f >> 4) * 17 + (f & 15)];
    }
}

// ---------------- kernel: build CSR ----------------
__global__ void k_csr(const float* __restrict__ wih, const float* __restrict__ whh) {
    int warp = threadIdx.x >> 5;
    int lane = threadIdx.x & 31;
    int gr = blockIdx.x * 8 + warp;
    if (gr >= 3 * HID) return;
    int m = gr / HID;
    int row = gr % HID;
    const float* src;
    int ncol;
    if (m == 0) { src = wih + (size_t)row * INP; ncol = INP; }
    else        { src = whh + ((size_t)(m - 1) * HID + row) * HID; ncol = HID; }
    int base = 0;
    for (int c0 = 0; c0 < ncol; c0 += 32) {
        float w = src[c0 + lane];
        unsigned mask = __ballot_sync(0xffffffffu, w != 0.0f);
        if (w != 0.0f) {
            int pos = base + __popc(mask & ((1u << lane) - 1u));
            if (pos < MAXNZ) {
                g_idx[m][row][pos] = (unsigned short)(c0 + lane);
                g_val[m][row][pos] = w;
            }
        }
        base += __popc(mask);
    }
    int cnt = base < MAXNZ ? base : MAXNZ;
    int rcnt = (cnt + 3) & ~3;
    for (int p = cnt + lane; p < rcnt; p += 32) {
        g_idx[m][row][p] = 0;
        g_val[m][row][p] = 0.0f;
    }
    if (lane == 0) g_cnt[m][row] = rcnt;
}

// ---------------- kernel: transpose out_w ----------------
__global__ void k_wT(const float* __restrict__ ow) {
    __shared__ float tl[32][33];
    int i0 = blockIdx.x * 32, o0 = blockIdx.y * 32;
    int tx = threadIdx.x, ty = threadIdx.y;
    tl[ty][tx] = ow[(size_t)(o0 + ty) * HID + i0 + tx];
    __syncthreads();
    g_WT[(size_t)(i0 + ty) * INP + o0 + tx] = tl[tx][ty];
}

// ---------------- persistent recurrence kernel (merged layers) ----------------
// 64 CTAs. CTA c owns rows [16c, 16c+16) of BOTH layers.
// Phase p: compute h0(p) (p<SEQ) and h1(p-1) (p>=1). All inputs of phase p
// were produced in phase p-1 -> ONE barrier per phase.
__global__ void __launch_bounds__(NTHR, 1) k_rnn() {
    __shared__ unsigned short sIdxX[16][MAXNZ];  // ih0
    __shared__ float          sValX[16][MAXNZ];
    __shared__ unsigned short sIdx0[16][MAXNZ];  // hh0
    __shared__ float          sVal0[16][MAXNZ];
    __shared__ unsigned short sIdx1[16][MAXNZ];  // hh1
    __shared__ float          sVal1[16][MAXNZ];
    __shared__ int sC[3][16];

    int cta = blockIdx.x;
    int r0 = cta * 16;

    for (int e = threadIdx.x; e < 16 * MAXNZ; e += NTHR) {
        int rr = e >> 6, kk = e & 63;
        sIdxX[rr][kk] = g_idx[0][r0 + rr][kk];
        sValX[rr][kk] = g_val[0][r0 + rr][kk];
        sIdx0[rr][kk] = g_idx[1][r0 + rr][kk];
        sVal0[rr][kk] = g_val[1][r0 + rr][kk];
        sIdx1[rr][kk] = g_idx[2][r0 + rr][kk];
        sVal1[rr][kk] = g_val[2][r0 + rr][kk];
    }
    if (threadIdx.x < 48) {
        int m = threadIdx.x / 16, rr = threadIdx.x & 15;
        sC[m][rr] = g_cnt[m][r0 + rr];
    }
    __syncthreads();

    int warp = threadIdx.x >> 5;
    int lane = threadIdx.x & 31;
    int il = 2 * warp + (lane >> 4);   // local neuron 0..15
    int b  = lane & 15;                // batch
    int i  = r0 + il;
    int cX = sC[0][il];
    int c0 = sC[1][il];
    int c1 = sC[2][il];

    // prefetch ffx(0)
    float ffx;
    {
        const float* xp = g_xT + b;
        float a0 = 0.0f, a1 = 0.0f;
        for (int k = 0; k < cX; k += 4) {
            int j0 = sIdxX[il][k], j1 = sIdxX[il][k+1], j2 = sIdxX[il][k+2], j3 = sIdxX[il][k+3];
            float v0 = sValX[il][k], v1 = sValX[il][k+1], v2 = sValX[il][k+2], v3 = sValX[il][k+3];
            a0 += v0 * __ldg(xp + (j0 << 4));
            a1 += v1 * __ldg(xp + (j1 << 4));
            a0 += v2 * __ldg(xp + (j2 << 4));
            a1 += v3 * __ldg(xp + (j3 << 4));
        }
        ffx = a0 + a1;
    }

    for (int p = 0; p <= SEQ; p++) {
        if (p > 0) wait_all((unsigned)p);

        const float* hprev = g_h0[(p + 1) & 1] + b;   // h0(p-1)

        // ---- layer 0: h0(p) ----
        if (p < SEQ) {
            float acc0 = SQRT10 + ffx, acc1 = 0.0f;
            if (p > 0) {
                for (int k = 0; k < c0; k += 4) {
                    int j0 = sIdx0[il][k], j1 = sIdx0[il][k+1], j2 = sIdx0[il][k+2], j3 = sIdx0[il][k+3];
                    float v0 = sVal0[il][k], v1 = sVal0[il][k+1], v2 = sVal0[il][k+2], v3 = sVal0[il][k+3];
                    acc0 += v0 * __ldcg(hprev + (j0 << 4));
                    acc1 += v1 * __ldcg(hprev + (j1 << 4));
                    acc0 += v2 * __ldcg(hprev + (j2 << 4));
                    acc1 += v3 * __ldcg(hprev + (j3 << 4));
                }
            }
            __stcg(&g_h0[p & 1][i * 16 + b], fmaxf(acc0 + acc1, 0.0f));
        }

        // ---- layer 1: h1(p-1) = relu(c + Whh1*(h0(p-1) + h1(p-2))) ----
        if (p >= 1) {
            int t1 = p - 1;
            float acc0 = SQRT10, acc1 = 0.0f;
            if (t1 > 0) {
                const float* h1p = g_outsT + (size_t)(t1 - 1) * (HID * BATCH) + b;
                for (int k = 0; k < c1; k += 4) {
                    int j0 = sIdx1[il][k], j1 = sIdx1[il][k+1], j2 = sIdx1[il][k+2], j3 = sIdx1[il][k+3];
                    float v0 = sVal1[il][k], v1 = sVal1[il][k+1], v2 = sVal1[il][k+2], v3 = sVal1[il][k+3];
                    float s0 = __ldcg(hprev + (j0 << 4)) + __ldcg(h1p + (j0 << 4));
                    float s1 = __ldcg(hprev + (j1 << 4)) + __ldcg(h1p + (j1 << 4));
                    float s2 = __ldcg(hprev + (j2 << 4)) + __ldcg(h1p + (j2 << 4));
                    float s3 = __ldcg(hprev + (j3 << 4)) + __ldcg(h1p + (j3 << 4));
                    acc0 += v0 * s0;
                    acc1 += v1 * s1;
                    acc0 += v2 * s2;
                    acc1 += v3 * s3;
                }
            } else {
                for (int k = 0; k < c1; k += 4) {
                    int j0 = sIdx1[il][k], j1 = sIdx1[il][k+1], j2 = sIdx1[il][k+2], j3 = sIdx1[il][k+3];
                    float v0 = sVal1[il][k], v1 = sVal1[il][k+1], v2 = sVal1[il][k+2], v3 = sVal1[il][k+3];
                    acc0 += v0 * __ldcg(hprev + (j0 << 4));
                    acc1 += v1 * __ldcg(hprev + (j1 << 4));
                    acc0 += v2 * __ldcg(hprev + (j2 << 4));
                    acc1 += v3 * __ldcg(hprev + (j3 << 4));
                }
            }
            __stcg(&g_outsT[(size_t)t1 * (HID * BATCH) + i * 16 + b], fmaxf(acc0 + acc1, 0.0f));
        }

        __syncthreads();
        if (threadIdx.x == 0 && p < SEQ) st_rel(&g_slots[cta], (unsigned)(p + 1));

        // prefetch ffx(p+1) AFTER release -> x latency overlaps barrier turnaround
        if (p + 1 < SEQ) {
            const float* xp = g_xT + (size_t)(p + 1) * (INP * BATCH) + b;
            float a0 = 0.0f, a1 = 0.0f;
            for (int k = 0; k < cX; k += 4) {
                int j0 = sIdxX[il][k], j1 = sIdxX[il][k+1], j2 = sIdxX[il][k+2], j3 = sIdxX[il][k+3];
                float v0 = sValX[il][k], v1 = sValX[il][k+1], v2 = sValX[il][k+2], v3 = sValX[il][k+3];
                a0 += v0 * __ldg(xp + (j0 << 4));
                a1 += v1 * __ldg(xp + (j1 << 4));
                a0 += v2 * __ldg(xp + (j2 << 4));
                a1 += v3 * __ldg(xp + (j3 << 4));
            }
            ffx = a0 + a1;
        }
    }
}

// ---------------- projection: out[b][t][o] = sum_i h1[t][i][b]*W[o][i] + bias[o] ----------------
__global__ void __launch_bounds__(NTHR) k_proj(const float* __restrict__ ob, float* __restrict__ out) {
    __shared__ float sh[512 * BATCH];
    int t = blockIdx.x;
    int o = threadIdx.x;
    float bias = __ldg(ob + o);
    unsigned long long acc[8];
    #pragma unroll
    for (int j = 0; j < 8; j++) acc[j] = pk2(bias, bias);
    #pragma unroll
    for (int half = 0; half < 2; half++) {
        __syncthreads();
        const float* src = g_outsT + (size_t)t * (HID * BATCH) + half * (512 * BATCH);
        for (int e = threadIdx.x; e < 512 * BATCH; e += NTHR) sh[e] = src[e];
        __syncthreads();
        const float* wcol = g_WT + (size_t)(half * 512) * INP + o;
        #pragma unroll 2
        for (int i = 0; i < 512; i++) {
            float w = __ldg(wcol + (size_t)i * INP);
            unsigned long long wp = pk2(w, w);
            const unsigned long long* hp = (const unsigned long long*)(sh + i * BATCH);
            fma2(acc[0], hp[0], wp);
            fma2(acc[1], hp[1], wp);
            fma2(acc[2], hp[2], wp);
            fma2(acc[3], hp[3], wp);
            fma2(acc[4], hp[4], wp);
            fma2(acc[5], hp[5], wp);
            fma2(acc[6], hp[6], wp);
            fma2(acc[7], hp[7], wp);
        }
    }
    #pragma unroll
    for (int j = 0; j < 8; j++) {
        float lo, hi;
        upk2(acc[j], lo, hi);
        out[((size_t)(2 * j)     * SEQ + t) * INP + o] = lo;
        out[((size_t)(2 * j + 1) * SEQ + t) * INP + o] = hi;
    }
}

// ---------------- final hidden state h_T [l][b][i] ----------------
__global__ void k_ht(float* __restrict__ out) {
    int e = blockIdx.x * blockDim.x + threadIdx.x;
    if (e >= HT_ELEMS) return;
    int l = e / (BATCH * HID);
    int r = e % (BATCH * HID);
    int b = r / HID;
    int i = r % HID;
    float v;
    if (l == 0) v = g_h0[(SEQ - 1) & 1][i * 16 + b];
    else        v = g_outsT[(size_t)(SEQ - 1) * (HID * BATCH) + i * 16 + b];
    out[(size_t)OUT_MAIN + e] = v;
}

// ---------------- launch ----------------
extern "C" void kernel_launch(void* const* d_in, const int* in_sizes, int n_in,
                              void* d_out, int out_size) {
    const float* x   = (const float*)d_in[0];
    const float* wih = (const float*)d_in[1];
    const float* whh = (const float*)d_in[2];
    const float* ow  = (const float*)d_in[3];
    const float* ob  = (const float*)d_in[4];
    float* out = (float*)d_out;

    k_zero_slots<<<1, NCTA>>>();
    k_xT<<<SEQ, 256>>>(x);
    k_csr<<<(3 * HID) / 8, 256>>>(wih, whh);
    k_wT<<<dim3(HID / 32, INP / 32), dim3(32, 32)>>>(ow);
    k_rnn<<<NCTA, NTHR>>>();
    k_proj<<<SEQ, NTHR>>>(ob, out);
    if (out_size >= OUT_MAIN + HT_ELEMS) {
        k_ht<<<(HT_ELEMS + 511) / 512, 512>>>(out);
    }
}